// round 8
// baseline (speedup 1.0000x reference)
#include <cuda_runtime.h>

#define DEPTH   8
#define NCLASS  10
#define NT      64
#define NREG    32    // float2 elements per thread; NT*NREG = 2048 = DIM/2
#define BATCH   4096
#define NBLK    888   // 148 SMs * 6 resident blocks

typedef unsigned long long u64;

// GF(2)-linear element swizzle (conflict-free u64 LDS/STS for all patterns).
__device__ __host__ constexpr int Sz(int e) {
    return e ^ ((e >> 5) & 15) ^ (((e >> 10) & 1) << 3);
}
// CNOT-layer composite map in element space: old_e = Emap(new_e).
__device__ __host__ constexpr int Emap(int e) {
    return e ^ (e >> 1) ^ ((e >> 2) & 0x2AA);
}
__device__ __host__ constexpr int CBr(int r)  { return (r << 5) ^ (r & 15); } // Sz(r<<5)
__device__ __host__ constexpr int CGr(int r)  { return Emap(r); }             // Sz(Emap(r)), r<32
__device__ __host__ constexpr bool SWP(int r) { return ((r ^ (r >> 1)) & 1) != 0; }

#define PACK2(d,x,y)   asm("mov.b64 %0,{%1,%2};" : "=l"(d) : "f"(x),"f"(y))
#define UNPACK2(x,y,d) asm("mov.b64 {%0,%1},%2;" : "=f"(x),"=f"(y) : "l"(d))
#define MUL2(d,a,b)    asm("mul.rn.f32x2 %0,%1,%2;" : "=l"(d) : "l"(a),"l"(b))
#define FMA2(d,a,b,c)  asm("fma.rn.f32x2 %0,%1,%2,%3;" : "=l"(d) : "l"(a),"l"(b),"l"(c))

// Packed lifting RY butterfly on 32 u64 regs along register-bit mask m.
__device__ __forceinline__ void lift32(u64* P, int m, u64 NP2, u64 S2) {
#pragma unroll
    for (int k = 0; k < NREG; k++)
        if (!(k & m)) {
            u64 U, V;
            FMA2(U, NP2, P[k | m], P[k]);      // u  = a0 - p*a1
            FMA2(V, S2,  U,        P[k | m]);  // a1'= a1 + s*u
            FMA2(P[k], NP2, V, U);             // a0'= u - p*a1'
            P[k | m] = V;
        }
}

__global__ __launch_bounds__(NT, 6) void vqc_kernel(const float* __restrict__ X,
                                                    const float* __restrict__ W,
                                                    float* __restrict__ out) {
    __shared__ u64 smP[2048];                         // store-B / gather buffer
    __shared__ u64 smQ[2048];                         // store-A / load-B buffer
    __shared__ u64 SS2[DEPTH * 12], PP2[DEPTH * 12];  // packed sin / -tan(phi/2)
    __shared__ float c0s[DEPTH], s0s[DEPTH];          // scalar coeffs, qubit 0
    __shared__ float np11s[DEPTH], s11s[DEPTH];       // scalar coeffs, qubit 11
    __shared__ float enc0[12], enc1[12];
    __shared__ float red[2][NCLASS];

    const int t = threadIdx.x;

    // ---- coefficient tables: built ONCE per persistent block ----
    for (int i = t; i < DEPTH * 12; i += NT) {
        float s_, c_;
        sincosf(0.5f * W[i], &s_, &c_);
        float np = -s_ / (1.0f + c_);
        u64 b2, c3;
        PACK2(b2, s_, s_);  PACK2(c3, np, np);
        SS2[i] = b2;  PP2[i] = c3;
        const int q = i % 12, k = i / 12;
        if (q == 0)  { c0s[k] = c_;  s0s[k] = s_; }
        if (q == 11) { np11s[k] = np; s11s[k] = s_; }
    }

    // ---- per-thread address bases (all maps GF(2)-linear) ----
    // Tiling A: e = (t<<5)|r   (regs = e4..0 -> qubits 6..10)
    // Tiling B: e = (t0<<10)|(r<<5)|((t>>1)&31)  (regs = e9..5 -> qubits 1..5)
    const int bA = (t << 5) ^ (t & 15) ^ (((t >> 5) & 1) << 3);
    const int bB = (((t & 1) << 10) | ((t >> 1) & 31)) ^ ((t & 1) << 3);
    int em = t << 5;
    em = em ^ (em >> 1) ^ ((em >> 2) & 0x2AA);
    const int bG = Sz(em);

    // ---- persistent sample loop ----
    for (int s = blockIdx.x; s < BATCH; s += NBLK) {

        if (t < 12) {
            float s_, c_;
            sincosf(0.5f * X[s * 12 + t], &s_, &c_);
            const float rr = 0.7071067811865476f;
            enc0[t] = (c_ - s_) * rr;
            enc1[t] = (c_ + s_) * rr;
        }
        __syncthreads();

        // ---- init: product state (H + encoding RY) in tiling B registers ----
        // thread bits: q0<-t0, q6<-t5, q7<-t4, q8<-t3, q9<-t2, q10<-t1
        float base = (t & 1)        ? enc1[0]  : enc0[0];
        base *= ((t >> 5) & 1)      ? enc1[6]  : enc0[6];
        base *= ((t >> 4) & 1)      ? enc1[7]  : enc0[7];
        base *= ((t >> 3) & 1)      ? enc1[8]  : enc0[8];
        base *= ((t >> 2) & 1)      ? enc1[9]  : enc0[9];
        base *= ((t >> 1) & 1)      ? enc1[10] : enc0[10];
        const float bx = base * enc0[11], by = base * enc1[11];

        u64 P[NREG];
#pragma unroll
        for (int r = 0; r < NREG; r++) {
            // reg bits: q1<-r4, q2<-r3, q3<-r2, q4<-r1, q5<-r0
            float rf = (r & 16) ? enc1[1] : enc0[1];
            rf *= (r & 8) ? enc1[2] : enc0[2];
            rf *= (r & 4) ? enc1[3] : enc0[3];
            rf *= (r & 2) ? enc1[4] : enc0[4];
            rf *= (r & 1) ? enc1[5] : enc0[5];
            float x = rf * bx, y = rf * by;
            PACK2(P[r], x, y);
        }

#pragma unroll 1
        for (int k = 0; k < DEPTH; k++) {
            const int kc = k * 12;

            // ---- trip 1: store B(smP) -> gather (CNOT perm) + q11 -> q6..q10
#pragma unroll
            for (int r = 0; r < NREG; r++)
                smP[bB ^ CBr(r)] = P[r];
            __syncthreads();                   // store-B visible before gather

            const float np11 = np11s[k];
            const float s11  = s11s[k];
#pragma unroll
            for (int r = 0; r < NREG; r++) {
                float2 L = ((const float2*)smP)[bG ^ CGr(r)];
                float x = SWP(r) ? L.y : L.x;
                float y = SWP(r) ? L.x : L.y;
                // SIMD qubit 11 (lifting, scalar)
                float u = fmaf(np11, y, x);
                float v = fmaf(s11, u, y);
                float w = fmaf(np11, v, u);
                PACK2(P[r], w, v);
            }
            __syncthreads();                   // gather reads done before store-A
            lift32(P, 16, PP2[kc + 6],  SS2[kc + 6]);   // q6  <-> r4
            lift32(P, 8,  PP2[kc + 7],  SS2[kc + 7]);   // q7
            lift32(P, 4,  PP2[kc + 8],  SS2[kc + 8]);   // q8
            lift32(P, 2,  PP2[kc + 9],  SS2[kc + 9]);   // q9
            lift32(P, 1,  PP2[kc + 10], SS2[kc + 10]);  // q10

            // ---- trip 2: store A(smQ) -> load B(smQ) -> q1..q5 + shfl q0 ----
#pragma unroll
            for (int r = 0; r < NREG; r++)
                smQ[bA ^ r] = P[r];
            __syncthreads();                   // store-A visible before load-B
#pragma unroll
            for (int r = 0; r < NREG; r++)
                P[r] = smQ[bB ^ CBr(r)];

            lift32(P, 16, PP2[kc + 1], SS2[kc + 1]);    // q1 <-> r4
            lift32(P, 8,  PP2[kc + 2], SS2[kc + 2]);
            lift32(P, 4,  PP2[kc + 3], SS2[kc + 3]);
            lift32(P, 2,  PP2[kc + 4], SS2[kc + 4]);
            lift32(P, 1,  PP2[kc + 5], SS2[kc + 5]);

            // qubit 0 on lane bit t0: butterfly via shfl_xor
            {
                const float c0 = c0s[k];
                const float s0 = s0s[k];
                const float se = (t & 1) ? s0 : -s0;
                u64 C2x, SE2;
                PACK2(C2x, c0, c0);
                PACK2(SE2, se, se);
#pragma unroll
                for (int r = 0; r < NREG; r++) {
                    u64 part = __shfl_xor_sync(0xffffffffu, P[r], 1);
                    u64 tm;
                    MUL2(tm, SE2, part);
                    FMA2(P[r], C2x, P[r], tm);
                }
            }
        }

        // ---- measurement from registers (tiling B) ----
        float T = 0.0f, A1 = 0.0f, A2 = 0.0f, A3 = 0.0f, A4 = 0.0f, A5 = 0.0f;
#pragma unroll
        for (int r = 0; r < NREG; r++) {
            float x, y;
            UNPACK2(x, y, P[r]);
            float p2 = fmaf(y, y, x * x);
            T += p2;
            if (!(r & 16)) A1 += p2;
            if (!(r & 8))  A2 += p2;
            if (!(r & 4))  A3 += p2;
            if (!(r & 2))  A4 += p2;
            if (!(r & 1))  A5 += p2;
        }
        float loc[NCLASS];
        loc[0] = (t & 1)        ? -T : T;
        loc[1] = 2.0f * A1 - T;
        loc[2] = 2.0f * A2 - T;
        loc[3] = 2.0f * A3 - T;
        loc[4] = 2.0f * A4 - T;
        loc[5] = 2.0f * A5 - T;
        loc[6] = ((t >> 5) & 1) ? -T : T;
        loc[7] = ((t >> 4) & 1) ? -T : T;
        loc[8] = ((t >> 3) & 1) ? -T : T;
        loc[9] = ((t >> 2) & 1) ? -T : T;

#pragma unroll
        for (int p = 0; p < NCLASS; p++) {
            float v = loc[p];
#pragma unroll
            for (int o = 16; o > 0; o >>= 1)
                v += __shfl_xor_sync(0xffffffffu, v, o);
            if ((t & 31) == 0) red[t >> 5][p] = v;
        }
        __syncthreads();
        if (t < NCLASS)
            out[s * NCLASS + t] = red[0][t] + red[1][t];
        __syncthreads();   // red/enc reuse guard for next sample
    }
}

extern "C" void kernel_launch(void* const* d_in, const int* in_sizes, int n_in,
                              void* d_out, int out_size) {
    const float* X = (const float*)d_in[0];   // [4096, 12] fp32
    const float* W = (const float*)d_in[1];   // [8, 12]    fp32
    float* out = (float*)d_out;               // [4096, 10] fp32
    vqc_kernel<<<NBLK, NT>>>(X, W, out);
}

// round 9
// speedup vs baseline: 1.2581x; 1.2581x over previous
#include <cuda_runtime.h>

#define DEPTH   8
#define NCLASS  10
#define NT      64
#define NREG    32    // float2 elements per thread; NT*NREG = 2048 = DIM/2

typedef unsigned long long u64;

// GF(2)-linear element swizzle (conflict-free u64 LDS/STS for all patterns).
__device__ __host__ constexpr int Sz(int e) {
    return e ^ ((e >> 5) & 15) ^ (((e >> 10) & 1) << 3);
}
// CNOT-layer composite map in element space: old_e = Emap(new_e).
__device__ __host__ constexpr int Emap(int e) {
    return e ^ (e >> 1) ^ ((e >> 2) & 0x2AA);
}
__device__ __host__ constexpr int CBr(int r)  { return (r << 5) ^ (r & 15); } // Sz(r<<5)
__device__ __host__ constexpr int CGr(int r)  { return Emap(r); }             // Sz(Emap(r)), r<32
__device__ __host__ constexpr bool SWP(int r) { return ((r ^ (r >> 1)) & 1) != 0; }

#define PACK2(d,x,y)   asm("mov.b64 %0,{%1,%2};" : "=l"(d) : "f"(x),"f"(y))
#define UNPACK2(x,y,d) asm("mov.b64 {%0,%1},%2;" : "=f"(x),"=f"(y) : "l"(d))
#define MUL2(d,a,b)    asm("mul.rn.f32x2 %0,%1,%2;" : "=l"(d) : "l"(a),"l"(b))
#define FMA2(d,a,b,c)  asm("fma.rn.f32x2 %0,%1,%2,%3;" : "=l"(d) : "l"(a),"l"(b),"l"(c))

// Scaled-shear RY butterfly on 32 u64 regs along register-bit mask m.
// [b0;b1] = [[1,-p],[p,1]]·[a0;a1], p = tan(phi/2). cos factor applied
// once per layer via the C_k scale. Both FMAs independent (chain depth 1).
__device__ __forceinline__ void shear32(u64* P, int m, u64 T2, u64 NT2) {
#pragma unroll
    for (int k = 0; k < NREG; k++)
        if (!(k & m)) {
            u64 n0, n1;
            FMA2(n0, NT2, P[k | m], P[k]);     // b0 = a0 - p*a1
            FMA2(n1, T2,  P[k],     P[k | m]); // b1 = a1 + p*a0
            P[k]     = n0;
            P[k | m] = n1;
        }
}

__global__ __launch_bounds__(NT, 6) void vqc_kernel(const float* __restrict__ X,
                                                    const float* __restrict__ W,
                                                    float* __restrict__ out) {
    __shared__ u64 smP[2048];                         // store-B / gather buffer
    __shared__ u64 smQ[2048];                         // store-A / load-B buffer
    __shared__ u64 TT2[DEPTH * 12], NT2s[DEPTH * 12]; // packed tan / -tan
    __shared__ float t0s[DEPTH];                      // scalar tan, qubit 0
    __shared__ float t11s[DEPTH];                     // scalar tan, qubit 11
    __shared__ u64 CL2[DEPTH];                        // packed per-layer cos product
    __shared__ float enc0[12], enc1[12];
    __shared__ float red[2][NCLASS];

    const int t = threadIdx.x;

    // ---- coefficient tables ----
    for (int i = t; i < DEPTH * 12; i += NT) {
        float s_, c_;
        sincosf(0.5f * W[i], &s_, &c_);
        float tp = s_ / c_;                   // tan(phi/2)
        float nt = -tp;
        u64 a, b;
        PACK2(a, tp, tp);  PACK2(b, nt, nt);
        TT2[i] = a;  NT2s[i] = b;
        const int q = i % 12, k = i / 12;
        if (q == 0)  t0s[k]  = tp;
        if (q == 11) t11s[k] = tp;
    }
    if (t < DEPTH) {                          // per-layer cos product
        float C = 1.0f;
#pragma unroll
        for (int q = 0; q < 12; q++)
            C *= cosf(0.5f * W[t * 12 + q]);
        u64 c2;
        PACK2(c2, C, C);
        CL2[t] = c2;
    }
    if (t < 12) {
        float s_, c_;
        sincosf(0.5f * X[blockIdx.x * 12 + t], &s_, &c_);
        const float rr = 0.7071067811865476f;
        enc0[t] = (c_ - s_) * rr;
        enc1[t] = (c_ + s_) * rr;
    }
    __syncthreads();

    // ---- per-thread address bases (all maps GF(2)-linear) ----
    // Tiling A: e = (t<<5)|r   (regs = e4..0 -> qubits 6..10)
    // Tiling B: e = (t0<<10)|(r<<5)|((t>>1)&31)  (regs = e9..5 -> qubits 1..5)
    const int bA = (t << 5) ^ (t & 15) ^ (((t >> 5) & 1) << 3);
    const int bB = (((t & 1) << 10) | ((t >> 1) & 31)) ^ ((t & 1) << 3);
    int em = t << 5;
    em = em ^ (em >> 1) ^ ((em >> 2) & 0x2AA);
    const int bG = Sz(em);

    // ---- init: product state (H + encoding RY) in tiling B registers ----
    // thread bits: q0<-t0, q6<-t5, q7<-t4, q8<-t3, q9<-t2, q10<-t1
    float base = (t & 1)        ? enc1[0]  : enc0[0];
    base *= ((t >> 5) & 1)      ? enc1[6]  : enc0[6];
    base *= ((t >> 4) & 1)      ? enc1[7]  : enc0[7];
    base *= ((t >> 3) & 1)      ? enc1[8]  : enc0[8];
    base *= ((t >> 2) & 1)      ? enc1[9]  : enc0[9];
    base *= ((t >> 1) & 1)      ? enc1[10] : enc0[10];
    const float bx = base * enc0[11], by = base * enc1[11];

    u64 P[NREG];
#pragma unroll
    for (int r = 0; r < NREG; r++) {
        // reg bits: q1<-r4, q2<-r3, q3<-r2, q4<-r1, q5<-r0
        float rf = (r & 16) ? enc1[1] : enc0[1];
        rf *= (r & 8) ? enc1[2] : enc0[2];
        rf *= (r & 4) ? enc1[3] : enc0[3];
        rf *= (r & 2) ? enc1[4] : enc0[4];
        rf *= (r & 1) ? enc1[5] : enc0[5];
        float x = rf * bx, y = rf * by;
        PACK2(P[r], x, y);
    }

#pragma unroll 1
    for (int k = 0; k < DEPTH; k++) {
        const int kc = k * 12;

        // ---- trip 1: store B(smP) -> gather + q11 shear + layer scale ----
#pragma unroll
        for (int r = 0; r < NREG; r++)
            smP[bB ^ CBr(r)] = P[r];
        __syncthreads();                       // store-B visible before gather

        const float t11 = t11s[k];
        const u64 C2 = CL2[k];
#pragma unroll
        for (int r = 0; r < NREG; r++) {
            float2 L = ((const float2*)smP)[bG ^ CGr(r)];
            float x = SWP(r) ? L.y : L.x;
            float y = SWP(r) ? L.x : L.y;
            // SIMD qubit 11: shear (both FMAs independent)
            float u = fmaf(-t11, y, x);
            float v = fmaf( t11, x, y);
            u64 pk;
            PACK2(pk, u, v);
            MUL2(P[r], C2, pk);                // per-layer cos-product scale
        }
        __syncthreads();                       // gather reads done before store-A
        shear32(P, 16, TT2[kc + 6],  NT2s[kc + 6]);   // q6  <-> r4
        shear32(P, 8,  TT2[kc + 7],  NT2s[kc + 7]);   // q7
        shear32(P, 4,  TT2[kc + 8],  NT2s[kc + 8]);   // q8
        shear32(P, 2,  TT2[kc + 9],  NT2s[kc + 9]);   // q9
        shear32(P, 1,  TT2[kc + 10], NT2s[kc + 10]);  // q10

        // ---- trip 2: store A(smQ) -> load B(smQ) -> q1..q5 + shfl q0 ----
#pragma unroll
        for (int r = 0; r < NREG; r++)
            smQ[bA ^ r] = P[r];
        __syncthreads();                       // store-A visible before load-B
#pragma unroll
        for (int r = 0; r < NREG; r++)
            P[r] = smQ[bB ^ CBr(r)];

        shear32(P, 16, TT2[kc + 1], NT2s[kc + 1]);    // q1 <-> r4
        shear32(P, 8,  TT2[kc + 2], NT2s[kc + 2]);
        shear32(P, 4,  TT2[kc + 3], NT2s[kc + 3]);
        shear32(P, 2,  TT2[kc + 4], NT2s[kc + 4]);
        shear32(P, 1,  TT2[kc + 5], NT2s[kc + 5]);

        // qubit 0 on lane bit t0: shear via shfl (1 FMA2 per reg)
        {
            const float t0c = t0s[k];
            const float te = (t & 1) ? t0c : -t0c;
            u64 TE2;
            PACK2(TE2, te, te);
#pragma unroll
            for (int r = 0; r < NREG; r++) {
                u64 part = __shfl_xor_sync(0xffffffffu, P[r], 1);
                FMA2(P[r], TE2, part, P[r]);   // b = a ± p*partner
            }
        }
    }

    // ---- measurement from registers (tiling B) ----
    float T = 0.0f, A1 = 0.0f, A2 = 0.0f, A3 = 0.0f, A4 = 0.0f, A5 = 0.0f;
#pragma unroll
    for (int r = 0; r < NREG; r++) {
        float x, y;
        UNPACK2(x, y, P[r]);
        float p2 = fmaf(y, y, x * x);
        T += p2;
        if (!(r & 16)) A1 += p2;
        if (!(r & 8))  A2 += p2;
        if (!(r & 4))  A3 += p2;
        if (!(r & 2))  A4 += p2;
        if (!(r & 1))  A5 += p2;
    }
    float loc[NCLASS];
    loc[0] = (t & 1)        ? -T : T;
    loc[1] = 2.0f * A1 - T;
    loc[2] = 2.0f * A2 - T;
    loc[3] = 2.0f * A3 - T;
    loc[4] = 2.0f * A4 - T;
    loc[5] = 2.0f * A5 - T;
    loc[6] = ((t >> 5) & 1) ? -T : T;
    loc[7] = ((t >> 4) & 1) ? -T : T;
    loc[8] = ((t >> 3) & 1) ? -T : T;
    loc[9] = ((t >> 2) & 1) ? -T : T;

#pragma unroll
    for (int p = 0; p < NCLASS; p++) {
        float v = loc[p];
#pragma unroll
        for (int o = 16; o > 0; o >>= 1)
            v += __shfl_xor_sync(0xffffffffu, v, o);
        if ((t & 31) == 0) red[t >> 5][p] = v;
    }
    __syncthreads();
    if (t < NCLASS)
        out[blockIdx.x * NCLASS + t] = red[0][t] + red[1][t];
}

extern "C" void kernel_launch(void* const* d_in, const int* in_sizes, int n_in,
                              void* d_out, int out_size) {
    const float* X = (const float*)d_in[0];   // [4096, 12] fp32
    const float* W = (const float*)d_in[1];   // [8, 12]    fp32
    float* out = (float*)d_out;               // [4096, 10] fp32
    const int batch = in_sizes[0] / 12;
    vqc_kernel<<<batch, NT>>>(X, W, out);
}

// round 10
// speedup vs baseline: 1.2617x; 1.0029x over previous
#include <cuda_runtime.h>

#define DEPTH   8
#define NCLASS  10
#define NT      64
#define NREG    32    // float2 elements per thread; NT*NREG = 2048 = DIM/2

typedef unsigned long long u64;

// GF(2)-linear element swizzle (conflict-free u64 LDS/STS for all patterns).
__device__ __host__ constexpr int Sz(int e) {
    return e ^ ((e >> 5) & 15) ^ (((e >> 10) & 1) << 3);
}
// CNOT-layer composite map in element space: old_e = Emap(new_e).
__device__ __host__ constexpr int Emap(int e) {
    return e ^ (e >> 1) ^ ((e >> 2) & 0x2AA);
}
__device__ __host__ constexpr int CBr(int r)  { return (r << 5) ^ (r & 15); } // Sz(r<<5)
__device__ __host__ constexpr int CGr(int r)  { return Emap(r); }             // Sz(Emap(r)), r<32
__device__ __host__ constexpr bool SWP(int r) { return ((r ^ (r >> 1)) & 1) != 0; }

#define PACK2(d,x,y)   asm("mov.b64 %0,{%1,%2};" : "=l"(d) : "f"(x),"f"(y))
#define UNPACK2(x,y,d) asm("mov.b64 {%0,%1},%2;" : "=f"(x),"=f"(y) : "l"(d))
#define MUL2(d,a,b)    asm("mul.rn.f32x2 %0,%1,%2;" : "=l"(d) : "l"(a),"l"(b))
#define FMA2(d,a,b,c)  asm("fma.rn.f32x2 %0,%1,%2,%3;" : "=l"(d) : "l"(a),"l"(b),"l"(c))

// Scaled-shear RY butterfly on 32 u64 regs along register-bit mask m.
// Both FMAs independent (chain depth 1 per qubit).
__device__ __forceinline__ void shear32(u64* P, int m, u64 T2, u64 NT2) {
#pragma unroll
    for (int k = 0; k < NREG; k++)
        if (!(k & m)) {
            u64 n0, n1;
            FMA2(n0, NT2, P[k | m], P[k]);     // b0 = a0 - p*a1
            FMA2(n1, T2,  P[k],     P[k | m]); // b1 = a1 + p*a0
            P[k]     = n0;
            P[k | m] = n1;
        }
}

__global__ __launch_bounds__(NT, 8) void vqc_kernel(const float* __restrict__ X,
                                                    const float* __restrict__ W,
                                                    float* __restrict__ out) {
    __shared__ u64 smP[2048];                         // store-B / gather buffer
    __shared__ u64 smQ[2048];                         // store-A / load-B buffer
    __shared__ u64 TT2[DEPTH * 12], NT2s[DEPTH * 12]; // packed tan / -tan
    __shared__ float t0s[DEPTH];                      // scalar tan, qubit 0
    __shared__ float t11s[DEPTH];                     // scalar tan, qubit 11
    __shared__ u64 CL2[DEPTH];                        // packed per-layer cos product
    __shared__ float enc0[12], enc1[12];
    __shared__ float red[2][NCLASS];

    const int t = threadIdx.x;

    // ---- coefficient tables ----
    for (int i = t; i < DEPTH * 12; i += NT) {
        float s_, c_;
        sincosf(0.5f * W[i], &s_, &c_);
        float tp = s_ / c_;                   // tan(phi/2)
        float nt = -tp;
        u64 a, b;
        PACK2(a, tp, tp);  PACK2(b, nt, nt);
        TT2[i] = a;  NT2s[i] = b;
        const int q = i % 12, k = i / 12;
        if (q == 0)  t0s[k]  = tp;
        if (q == 11) t11s[k] = tp;
    }
    if (t < DEPTH) {                          // per-layer cos product
        float C = 1.0f;
#pragma unroll
        for (int q = 0; q < 12; q++)
            C *= cosf(0.5f * W[t * 12 + q]);
        u64 c2;
        PACK2(c2, C, C);
        CL2[t] = c2;
    }
    if (t < 12) {
        float s_, c_;
        sincosf(0.5f * X[blockIdx.x * 12 + t], &s_, &c_);
        const float rr = 0.7071067811865476f;
        enc0[t] = (c_ - s_) * rr;
        enc1[t] = (c_ + s_) * rr;
    }
    __syncthreads();

    // ---- per-thread address bases (all maps GF(2)-linear) ----
    // Tiling A: e = (t<<5)|r   (regs = e4..0 -> qubits 6..10)
    // Tiling B: e = (t0<<10)|(r<<5)|((t>>1)&31)  (regs = e9..5 -> qubits 1..5)
    const int bA = (t << 5) ^ (t & 15) ^ (((t >> 5) & 1) << 3);
    const int bB = (((t & 1) << 10) | ((t >> 1) & 31)) ^ ((t & 1) << 3);
    int em = t << 5;
    em = em ^ (em >> 1) ^ ((em >> 2) & 0x2AA);
    const int bG = Sz(em);

    // ---- init: product state (H + encoding RY) in tiling B registers ----
    // thread bits: q0<-t0, q6<-t5, q7<-t4, q8<-t3, q9<-t2, q10<-t1
    float base = (t & 1)        ? enc1[0]  : enc0[0];
    base *= ((t >> 5) & 1)      ? enc1[6]  : enc0[6];
    base *= ((t >> 4) & 1)      ? enc1[7]  : enc0[7];
    base *= ((t >> 3) & 1)      ? enc1[8]  : enc0[8];
    base *= ((t >> 2) & 1)      ? enc1[9]  : enc0[9];
    base *= ((t >> 1) & 1)      ? enc1[10] : enc0[10];
    const float bx = base * enc0[11], by = base * enc1[11];

    u64 P[NREG];
#pragma unroll
    for (int r = 0; r < NREG; r++) {
        // reg bits: q1<-r4, q2<-r3, q3<-r2, q4<-r1, q5<-r0
        float rf = (r & 16) ? enc1[1] : enc0[1];
        rf *= (r & 8) ? enc1[2] : enc0[2];
        rf *= (r & 4) ? enc1[3] : enc0[3];
        rf *= (r & 2) ? enc1[4] : enc0[4];
        rf *= (r & 1) ? enc1[5] : enc0[5];
        float x = rf * bx, y = rf * by;
        PACK2(P[r], x, y);
    }

#pragma unroll 1
    for (int k = 0; k < DEPTH; k++) {
        const int kc = k * 12;

        // ---- trip 1: store B(smP) -> gather + q11 shear + layer scale ----
#pragma unroll
        for (int r = 0; r < NREG; r++)
            smP[bB ^ CBr(r)] = P[r];
        __syncthreads();                       // store-B visible before gather

        const float t11 = t11s[k];
        const u64 C2 = CL2[k];
        // two 16-load batches: halves peak outstanding-load register demand
#pragma unroll
        for (int h = 0; h < 2; h++) {
#pragma unroll
            for (int r0 = 0; r0 < 16; r0++) {
                const int r = h * 16 + r0;
                float2 L = ((const float2*)smP)[bG ^ CGr(r)];
                float x = SWP(r) ? L.y : L.x;
                float y = SWP(r) ? L.x : L.y;
                // SIMD qubit 11: shear (both FMAs independent)
                float u = fmaf(-t11, y, x);
                float v = fmaf( t11, x, y);
                u64 pk;
                PACK2(pk, u, v);
                MUL2(P[r], C2, pk);            // per-layer cos-product scale
            }
        }
        // NOTE: no barrier here — gather reads smP, store-A writes smQ
        // (disjoint); next smP write is next layer's store-B, which is
        // ordered by the post-store-A barrier below.
        shear32(P, 16, TT2[kc + 6],  NT2s[kc + 6]);   // q6  <-> r4
        shear32(P, 8,  TT2[kc + 7],  NT2s[kc + 7]);   // q7
        shear32(P, 4,  TT2[kc + 8],  NT2s[kc + 8]);   // q8
        shear32(P, 2,  TT2[kc + 9],  NT2s[kc + 9]);   // q9
        shear32(P, 1,  TT2[kc + 10], NT2s[kc + 10]);  // q10

        // ---- trip 2: store A(smQ) -> load B(smQ) -> q1..q5 + shfl q0 ----
#pragma unroll
        for (int r = 0; r < NREG; r++)
            smQ[bA ^ r] = P[r];
        __syncthreads();                       // store-A visible before load-B
#pragma unroll
        for (int r = 0; r < NREG; r++)
            P[r] = smQ[bB ^ CBr(r)];

        shear32(P, 16, TT2[kc + 1], NT2s[kc + 1]);    // q1 <-> r4
        shear32(P, 8,  TT2[kc + 2], NT2s[kc + 2]);
        shear32(P, 4,  TT2[kc + 3], NT2s[kc + 3]);
        shear32(P, 2,  TT2[kc + 4], NT2s[kc + 4]);
        shear32(P, 1,  TT2[kc + 5], NT2s[kc + 5]);

        // qubit 0 on lane bit t0: shear via shfl (1 FMA2 per reg)
        {
            const float t0c = t0s[k];
            const float te = (t & 1) ? t0c : -t0c;
            u64 TE2;
            PACK2(TE2, te, te);
#pragma unroll
            for (int r = 0; r < NREG; r++) {
                u64 part = __shfl_xor_sync(0xffffffffu, P[r], 1);
                FMA2(P[r], TE2, part, P[r]);   // b = a ± p*partner
            }
        }
    }

    // ---- measurement from registers (tiling B) ----
    float T = 0.0f, A1 = 0.0f, A2 = 0.0f, A3 = 0.0f, A4 = 0.0f, A5 = 0.0f;
#pragma unroll
    for (int r = 0; r < NREG; r++) {
        float x, y;
        UNPACK2(x, y, P[r]);
        float p2 = fmaf(y, y, x * x);
        T += p2;
        if (!(r & 16)) A1 += p2;
        if (!(r & 8))  A2 += p2;
        if (!(r & 4))  A3 += p2;
        if (!(r & 2))  A4 += p2;
        if (!(r & 1))  A5 += p2;
    }
    float loc[NCLASS];
    loc[0] = (t & 1)        ? -T : T;
    loc[1] = 2.0f * A1 - T;
    loc[2] = 2.0f * A2 - T;
    loc[3] = 2.0f * A3 - T;
    loc[4] = 2.0f * A4 - T;
    loc[5] = 2.0f * A5 - T;
    loc[6] = ((t >> 5) & 1) ? -T : T;
    loc[7] = ((t >> 4) & 1) ? -T : T;
    loc[8] = ((t >> 3) & 1) ? -T : T;
    loc[9] = ((t >> 2) & 1) ? -T : T;

#pragma unroll
    for (int p = 0; p < NCLASS; p++) {
        float v = loc[p];
#pragma unroll
        for (int o = 16; o > 0; o >>= 1)
            v += __shfl_xor_sync(0xffffffffu, v, o);
        if ((t & 31) == 0) red[t >> 5][p] = v;
    }
    __syncthreads();
    if (t < NCLASS)
        out[blockIdx.x * NCLASS + t] = red[0][t] + red[1][t];
}

extern "C" void kernel_launch(void* const* d_in, const int* in_sizes, int n_in,
                              void* d_out, int out_size) {
    const float* X = (const float*)d_in[0];   // [4096, 12] fp32
    const float* W = (const float*)d_in[1];   // [8, 12]    fp32
    float* out = (float*)d_out;               // [4096, 10] fp32
    const int batch = in_sizes[0] / 12;
    vqc_kernel<<<batch, NT>>>(X, W, out);
}

// round 11
// speedup vs baseline: 1.3188x; 1.0453x over previous
#include <cuda_runtime.h>

#define DEPTH   8
#define NCLASS  10
#define NT      64
#define NREG    32    // float2 elements per thread; NT*NREG = 2048 = DIM/2

typedef unsigned long long u64;

// GF(2)-linear element swizzle (conflict-free u64 LDS/STS for all patterns).
__device__ __host__ constexpr int Sz(int e) {
    return e ^ ((e >> 5) & 15) ^ (((e >> 10) & 1) << 3);
}
// CNOT-layer composite map in element space: old_e = Emap(new_e).
__device__ __host__ constexpr int Emap(int e) {
    return e ^ (e >> 1) ^ ((e >> 2) & 0x2AA);
}
__device__ __host__ constexpr int CBr(int r)  { return (r << 5) ^ (r & 15); } // Sz(r<<5)
__device__ __host__ constexpr int CGr(int r)  { return Emap(r); }             // Sz(Emap(r)), r<32
__device__ __host__ constexpr bool SWP(int r) { return ((r ^ (r >> 1)) & 1) != 0; }

#define PACK2(d,x,y)   asm("mov.b64 %0,{%1,%2};" : "=l"(d) : "f"(x),"f"(y))
#define UNPACK2(x,y,d) asm("mov.b64 {%0,%1},%2;" : "=f"(x),"=f"(y) : "l"(d))
#define MUL2(d,a,b)    asm("mul.rn.f32x2 %0,%1,%2;" : "=l"(d) : "l"(a),"l"(b))
#define FMA2(d,a,b,c)  asm("fma.rn.f32x2 %0,%1,%2,%3;" : "=l"(d) : "l"(a),"l"(b),"l"(c))

// Scaled-shear RY butterfly on 32 u64 regs along register-bit mask m.
// Both FMAs independent (chain depth 1 per qubit).
__device__ __forceinline__ void shear32(u64* P, int m, u64 T2, u64 NT2) {
#pragma unroll
    for (int k = 0; k < NREG; k++)
        if (!(k & m)) {
            u64 n0, n1;
            FMA2(n0, NT2, P[k | m], P[k]);     // b0 = a0 - p*a1
            FMA2(n1, T2,  P[k],     P[k | m]); // b1 = a1 + p*a0
            P[k]     = n0;
            P[k | m] = n1;
        }
}

__global__ __launch_bounds__(NT, 8) void vqc_kernel(const float* __restrict__ X,
                                                    const float* __restrict__ W,
                                                    float* __restrict__ out) {
    __shared__ u64 smB[2048];                         // SINGLE statevector buffer
    __shared__ u64 TT2[DEPTH * 12], NT2s[DEPTH * 12]; // packed tan / -tan
    __shared__ float t0s[DEPTH];                      // scalar tan, qubit 0
    __shared__ float t11s[DEPTH];                     // scalar tan, qubit 11
    __shared__ u64 CL2[DEPTH];                        // packed per-layer cos product
    __shared__ float enc0[12], enc1[12];
    __shared__ float red[2][NCLASS];

    const int t = threadIdx.x;

    // ---- coefficient tables ----
    for (int i = t; i < DEPTH * 12; i += NT) {
        float s_, c_;
        sincosf(0.5f * W[i], &s_, &c_);
        float tp = s_ / c_;                   // tan(phi/2)
        float nt = -tp;
        u64 a, b;
        PACK2(a, tp, tp);  PACK2(b, nt, nt);
        TT2[i] = a;  NT2s[i] = b;
        const int q = i % 12, k = i / 12;
        if (q == 0)  t0s[k]  = tp;
        if (q == 11) t11s[k] = tp;
    }
    if (t < DEPTH) {                          // per-layer cos product
        float C = 1.0f;
#pragma unroll
        for (int q = 0; q < 12; q++)
            C *= cosf(0.5f * W[t * 12 + q]);
        u64 c2;
        PACK2(c2, C, C);
        CL2[t] = c2;
    }
    if (t < 12) {
        float s_, c_;
        sincosf(0.5f * X[blockIdx.x * 12 + t], &s_, &c_);
        const float rr = 0.7071067811865476f;
        enc0[t] = (c_ - s_) * rr;
        enc1[t] = (c_ + s_) * rr;
    }
    __syncthreads();

    // ---- per-thread address bases (all maps GF(2)-linear) ----
    // Tiling A: e = (t<<5)|r   (regs = e4..0 -> qubits 6..10)
    // Tiling B: e = (t0<<10)|(r<<5)|((t>>1)&31)  (regs = e9..5 -> qubits 1..5)
    const int bA = (t << 5) ^ (t & 15) ^ (((t >> 5) & 1) << 3);
    const int bB = (((t & 1) << 10) | ((t >> 1) & 31)) ^ ((t & 1) << 3);
    int em = t << 5;
    em = em ^ (em >> 1) ^ ((em >> 2) & 0x2AA);
    const int bG = Sz(em);

    // ---- init: product state (H + encoding RY) in tiling B registers ----
    // thread bits: q0<-t0, q6<-t5, q7<-t4, q8<-t3, q9<-t2, q10<-t1
    float base = (t & 1)        ? enc1[0]  : enc0[0];
    base *= ((t >> 5) & 1)      ? enc1[6]  : enc0[6];
    base *= ((t >> 4) & 1)      ? enc1[7]  : enc0[7];
    base *= ((t >> 3) & 1)      ? enc1[8]  : enc0[8];
    base *= ((t >> 2) & 1)      ? enc1[9]  : enc0[9];
    base *= ((t >> 1) & 1)      ? enc1[10] : enc0[10];
    const float bx = base * enc0[11], by = base * enc1[11];

    u64 P[NREG];
#pragma unroll
    for (int r = 0; r < NREG; r++) {
        // reg bits: q1<-r4, q2<-r3, q3<-r2, q4<-r1, q5<-r0
        float rf = (r & 16) ? enc1[1] : enc0[1];
        rf *= (r & 8) ? enc1[2] : enc0[2];
        rf *= (r & 4) ? enc1[3] : enc0[3];
        rf *= (r & 2) ? enc1[4] : enc0[4];
        rf *= (r & 1) ? enc1[5] : enc0[5];
        float x = rf * bx, y = rf * by;
        PACK2(P[r], x, y);
    }

#pragma unroll 1
    for (int k = 0; k < DEPTH; k++) {
        const int kc = k * 12;

        // ---- trip 1: store B -> gather + q11 shear + layer scale ----
        // store-B writes the same per-thread address set that this thread's
        // previous load-B read -> intra-thread WAR only, no barrier needed.
#pragma unroll
        for (int r = 0; r < NREG; r++)
            smB[bB ^ CBr(r)] = P[r];
        __syncthreads();                       // store-B visible before gather

        const float t11 = t11s[k];
        const u64 C2 = CL2[k];
#pragma unroll
        for (int r = 0; r < NREG; r++) {
            float2 L = ((const float2*)smB)[bG ^ CGr(r)];
            float x = SWP(r) ? L.y : L.x;
            float y = SWP(r) ? L.x : L.y;
            // SIMD qubit 11: shear (both FMAs independent)
            float u = fmaf(-t11, y, x);
            float v = fmaf( t11, x, y);
            u64 pk;
            PACK2(pk, u, v);
            MUL2(P[r], C2, pk);                // per-layer cos-product scale
        }
        __syncthreads();                       // gather reads done before store-A
        shear32(P, 16, TT2[kc + 6],  NT2s[kc + 6]);   // q6  <-> r4
        shear32(P, 8,  TT2[kc + 7],  NT2s[kc + 7]);   // q7
        shear32(P, 4,  TT2[kc + 8],  NT2s[kc + 8]);   // q8
        shear32(P, 2,  TT2[kc + 9],  NT2s[kc + 9]);   // q9
        shear32(P, 1,  TT2[kc + 10], NT2s[kc + 10]);  // q10

        // ---- trip 2: store A -> load B (transpose) -> q1..q5 + shfl q0 ----
#pragma unroll
        for (int r = 0; r < NREG; r++)
            smB[bA ^ r] = P[r];
        __syncthreads();                       // store-A visible before load-B
#pragma unroll
        for (int r = 0; r < NREG; r++)
            P[r] = smB[bB ^ CBr(r)];

        shear32(P, 16, TT2[kc + 1], NT2s[kc + 1]);    // q1 <-> r4
        shear32(P, 8,  TT2[kc + 2], NT2s[kc + 2]);
        shear32(P, 4,  TT2[kc + 3], NT2s[kc + 3]);
        shear32(P, 2,  TT2[kc + 4], NT2s[kc + 4]);
        shear32(P, 1,  TT2[kc + 5], NT2s[kc + 5]);

        // qubit 0 on lane bit t0: shear via shfl (1 FMA2 per reg)
        {
            const float t0c = t0s[k];
            const float te = (t & 1) ? t0c : -t0c;
            u64 TE2;
            PACK2(TE2, te, te);
#pragma unroll
            for (int r = 0; r < NREG; r++) {
                u64 part = __shfl_xor_sync(0xffffffffu, P[r], 1);
                FMA2(P[r], TE2, part, P[r]);   // b = a ± p*partner
            }
        }
    }

    // ---- measurement from registers (tiling B) ----
    float T = 0.0f, A1 = 0.0f, A2 = 0.0f, A3 = 0.0f, A4 = 0.0f, A5 = 0.0f;
#pragma unroll
    for (int r = 0; r < NREG; r++) {
        float x, y;
        UNPACK2(x, y, P[r]);
        float p2 = fmaf(y, y, x * x);
        T += p2;
        if (!(r & 16)) A1 += p2;
        if (!(r & 8))  A2 += p2;
        if (!(r & 4))  A3 += p2;
        if (!(r & 2))  A4 += p2;
        if (!(r & 1))  A5 += p2;
    }
    float loc[NCLASS];
    loc[0] = (t & 1)        ? -T : T;
    loc[1] = 2.0f * A1 - T;
    loc[2] = 2.0f * A2 - T;
    loc[3] = 2.0f * A3 - T;
    loc[4] = 2.0f * A4 - T;
    loc[5] = 2.0f * A5 - T;
    loc[6] = ((t >> 5) & 1) ? -T : T;
    loc[7] = ((t >> 4) & 1) ? -T : T;
    loc[8] = ((t >> 3) & 1) ? -T : T;
    loc[9] = ((t >> 2) & 1) ? -T : T;

#pragma unroll
    for (int p = 0; p < NCLASS; p++) {
        float v = loc[p];
#pragma unroll
        for (int o = 16; o > 0; o >>= 1)
            v += __shfl_xor_sync(0xffffffffu, v, o);
        if ((t & 31) == 0) red[t >> 5][p] = v;
    }
    __syncthreads();
    if (t < NCLASS)
        out[blockIdx.x * NCLASS + t] = red[0][t] + red[1][t];
}

extern "C" void kernel_launch(void* const* d_in, const int* in_sizes, int n_in,
                              void* d_out, int out_size) {
    const float* X = (const float*)d_in[0];   // [4096, 12] fp32
    const float* W = (const float*)d_in[1];   // [8, 12]    fp32
    float* out = (float*)d_out;               // [4096, 10] fp32
    const int batch = in_sizes[0] / 12;
    vqc_kernel<<<batch, NT>>>(X, W, out);
}